// round 2
// baseline (speedup 1.0000x reference)
#include <cuda_runtime.h>
#include <cstdint>
#include <math.h>

#define C     64
#define S     512
#define P     4096
#define NB    32
#define NTOK  (NB * P)          // 131072
#define TOK   128               // tokens per block
#define TPB   256
#define SC    128               // codes per pass
#define NPASS (S / SC)

// output layout (float32, tuple flattened in order)
#define OFF_LOSS 0
#define OFF_IDX  1
#define OFF_OUT  (OFF_IDX + NTOK)
#define OFF_NCB  (OFF_OUT + NTOK * C)
#define OFF_CS   (OFF_NCB + S * C)
#define OFF_EW   (OFF_CS + S)

// ---------------- device scratch (no allocations allowed) ----------------
__device__ float g_cnorm[S];
__device__ float g_counts[S];
__device__ float g_dw[S * C];
__device__ float g_loss;
__device__ float g_cbT[C * S];   // codebook transposed [c][s]

// ---------------- helpers: packed f32x2 FMA (Blackwell) ----------------
__device__ __forceinline__ unsigned long long dup2(float f) {
    unsigned long long r;
    asm("mov.b64 %0, {%1, %1};" : "=l"(r) : "f"(f));
    return r;
}
__device__ __forceinline__ void fma2(unsigned long long& d,
                                     unsigned long long a,
                                     unsigned long long b) {
    asm("fma.rn.f32x2 %0, %1, %2, %0;" : "+l"(d) : "l"(a), "l"(b));
}
__device__ __forceinline__ float lo32(unsigned long long v) {
    return __uint_as_float((unsigned)(v & 0xffffffffull));
}
__device__ __forceinline__ float hi32(unsigned long long v) {
    return __uint_as_float((unsigned)(v >> 32));
}

// ---------------- prep: zero scratch, cnorm, transpose codebook ----------------
__global__ void vq_prep_kernel(const float* __restrict__ codebook) {
    int i = blockIdx.x * blockDim.x + threadIdx.x;
    if (i < S * C) {
        int s = i / C, c = i % C;
        float v = codebook[i];
        g_cbT[c * S + s] = v;
        g_dw[i] = 0.f;
    }
    if (i < S) {
        const float* row = codebook + i * C;
        // square-then-round, then sequential non-fused sum (mimic reference)
        float acc = 0.f;
        #pragma unroll
        for (int c = 0; c < C; c++)
            acc = __fadd_rn(acc, __fmul_rn(row[c], row[c]));
        g_cnorm[i] = acc;
        g_counts[i] = 0.f;
    }
    if (i == 0) g_loss = 0.f;
}

// ---------------- main: argmin + xq + loss + scatter ----------------
__global__ void __launch_bounds__(TPB, 2)
vq_main_kernel(const float* __restrict__ x,
               const float* __restrict__ codebook,
               float* __restrict__ outp) {
    extern __shared__ float sm[];
    float* tok  = sm;                         // [C][TOK]  8192 floats
    float* cbq  = sm + C * TOK;               // [C][SC]   8192  (cb tile, then xq tile)
    float* scn  = sm + 2 * C * TOK;           // [S]
    float* stn2 = sm + 2 * C * TOK + S;       // [TOK] token norms
    int*   sidx = (int*)(stn2 + TOK);         // [TOK]
    float* sred = (float*)(sidx + TOK);       // [TPB/32]

    const int tid = threadIdx.x;
    const int b   = blockIdx.x;
    const int n   = b >> 5;                   // P/TOK = 32 p-blocks per batch
    const int p0  = (b & 31) * TOK;
    const float* xb = x + (size_t)n * C * P + p0;

    for (int i = tid; i < S; i += TPB) scn[i] = g_cnorm[i];

    // token tile [c][t], coalesced along p
    for (int v = tid; v < C * TOK / 4; v += TPB) {
        int c = v >> 5;                        // 32 float4 per row
        int q = v & 31;
        *(float4*)(tok + c * TOK + q * 4) = *(const float4*)(xb + c * P + q * 4);
    }
    __syncthreads();

    // per-token ||t||^2, square-then-round + sequential non-fused add
    if (tid < TOK) {
        float a = 0.f;
        #pragma unroll
        for (int c = 0; c < C; c++) {
            float v = tok[c * TOK + tid];
            a = __fadd_rn(a, __fmul_rn(v, v));
        }
        stn2[tid] = a;
    }

    const int ty  = tid >> 4;
    const int tx  = tid & 15;
    const int ti0 = ty * 8;                    // 8 tokens
    const int j0  = tx * 8;                    // 8 codes

    float bestv[8];
    int   besti[8];
    #pragma unroll
    for (int i = 0; i < 8; i++) { bestv[i] = 3.4e38f; besti[i] = 0; }

    for (int pass = 0; pass < NPASS; pass++) {
        const int s0 = pass * SC;
        // load code tile [c][sj] from pre-transposed codebook (no smem transpose)
        for (int v = tid; v < C * SC / 4; v += TPB) {
            int c = v >> 5;
            int q = v & 31;
            *(float4*)(cbq + c * SC + q * 4) =
                *(const float4*)(g_cbT + c * S + s0 + q * 4);
        }
        __syncthreads();   // also orders stn2 writes before reads below

        unsigned long long acc[4][8];
        #pragma unroll
        for (int i = 0; i < 4; i++)
            #pragma unroll
            for (int j = 0; j < 8; j++) acc[i][j] = 0ull;

        #pragma unroll 4
        for (int k = 0; k < C; k++) {
            const float* tr = tok + k * TOK + ti0;
            ulonglong2 aA = *(const ulonglong2*)tr;       // {t0t1, t2t3}
            ulonglong2 aB = *(const ulonglong2*)(tr + 4); // {t4t5, t6t7}
            unsigned long long ap[4] = {aA.x, aA.y, aB.x, aB.y};
            const float* cr = cbq + k * SC + j0;
            float4 b0 = *(const float4*)cr;
            float4 b1 = *(const float4*)(cr + 4);
            unsigned long long bd[8] = {dup2(b0.x), dup2(b0.y), dup2(b0.z), dup2(b0.w),
                                        dup2(b1.x), dup2(b1.y), dup2(b1.z), dup2(b1.w)};
            #pragma unroll
            for (int j = 0; j < 8; j++)
                #pragma unroll
                for (int i = 0; i < 4; i++)
                    fma2(acc[i][j], ap[i], bd[j]);
        }

        // distances quantized EXACTLY like the reference:
        //   t1 = fl(A - 2B)   (fma: exact product, one rounding)
        //   d  = fl(t1 + Cn)  (forced separate rounding)
        #pragma unroll
        for (int j = 0; j < 8; j++) {
            int s = s0 + j0 + j;
            float cn = scn[s];
            #pragma unroll
            for (int i = 0; i < 4; i++) {
                int il = 2 * i, ih = il + 1;
                float tl = __fmaf_rn(-2.0f, lo32(acc[i][j]), stn2[ti0 + il]);
                float th = __fmaf_rn(-2.0f, hi32(acc[i][j]), stn2[ti0 + ih]);
                float dl = __fadd_rn(tl, cn);
                float dh = __fadd_rn(th, cn);
                if (dl < bestv[il] || (dl == bestv[il] && s < besti[il])) { bestv[il] = dl; besti[il] = s; }
                if (dh < bestv[ih] || (dh == bestv[ih] && s < besti[ih])) { bestv[ih] = dh; besti[ih] = s; }
            }
        }
        __syncthreads();
    }

    // reduce argmin across the 16 tx lanes (two independent 16-lane halves per warp)
    #pragma unroll
    for (int i = 0; i < 8; i++) {
        float v = bestv[i];
        int   sdx = besti[i];
        #pragma unroll
        for (int d = 8; d >= 1; d >>= 1) {
            float ov = __shfl_xor_sync(0xffffffffu, v, d);
            int   os = __shfl_xor_sync(0xffffffffu, sdx, d);
            if (ov < v || (ov == v && os < sdx)) { v = ov; sdx = os; }
        }
        if (tx == 0) sidx[ti0 + i] = sdx;
    }
    __syncthreads();

    // indices out + counts
    if (tid < TOK) {
        int sdx = sidx[tid];
        outp[OFF_IDX + (size_t)n * P + p0 + tid] = (float)sdx;
        atomicAdd(&g_counts[sdx], 1.0f);
    }

    // gather codebook rows into cbq[c][t] (coalesced 128B per token half) + dw scatter
    {
        int t  = tid >> 1;
        int c0 = (tid & 1) * 32;
        int sdx = sidx[t];
        const float4* crow = (const float4*)(codebook + sdx * C + c0);
        #pragma unroll
        for (int q = 0; q < 8; q++) {
            float4 w = crow[q];
            int c = c0 + q * 4;
            cbq[(c + 0) * TOK + t] = w.x;
            cbq[(c + 1) * TOK + t] = w.y;
            cbq[(c + 2) * TOK + t] = w.z;
            cbq[(c + 3) * TOK + t] = w.w;
        }
        float* dwrow = g_dw + sdx * C + c0;
        #pragma unroll 8
        for (int j = 0; j < 32; j++)
            atomicAdd(&dwrow[j], tok[(c0 + j) * TOK + t]);
    }
    __syncthreads();

    // straight-through output + commitment loss
    float lsum = 0.f;
    float* ob = outp + OFF_OUT + (size_t)n * C * P + p0;
    for (int v = tid; v < C * TOK; v += TPB) {
        int c = v >> 7;
        int t = v & 127;
        float xv = tok[c * TOK + t];
        float qv = cbq[c * TOK + t];
        ob[c * P + t] = xv + (qv - xv);        // matches x + stop_grad(xq - x)
        float dd = xv - qv;
        lsum = fmaf(dd, dd, lsum);
    }
    #pragma unroll
    for (int d = 16; d >= 1; d >>= 1) lsum += __shfl_xor_sync(0xffffffffu, lsum, d);
    if ((tid & 31) == 0) sred[tid >> 5] = lsum;
    __syncthreads();
    if (tid == 0) {
        float tot = 0.f;
        #pragma unroll
        for (int w = 0; w < TPB / 32; w++) tot += sred[w];
        atomicAdd(&g_loss, tot);
    }
}

// ---------------- finalize: EMA update + codebook renorm ----------------
__global__ void vq_finalize_kernel(const float* __restrict__ ema_w,
                                   const float* __restrict__ cluster_size,
                                   const int* __restrict__ steps_p,
                                   float* __restrict__ outp) {
    __shared__ float sred[S];
    int s = threadIdx.x;

    // robust "steps" decode (int32/int64 low word, or float32 fallback)
    int st = steps_p[0];
    if (st <= 0 || st > 1000000000) {
        float f = __int_as_float(st);
        st = (f > 0.5f && f < 1e9f) ? (int)(f + 0.5f) : 1;
    }
    float bias_corr = (float)(1.0 - pow(0.99, (double)st));

    float counts = g_counts[s];
    float cs_new = 0.99f * cluster_size[s] + 0.01f * counts;
    outp[OFF_CS + s] = cs_new;
    float cs_bc = cs_new / bias_corr;
    sred[s] = cs_bc;
    __syncthreads();
    #pragma unroll
    for (int d = 256; d >= 1; d >>= 1) {
        if (s < d) sred[s] += sred[s + d];
        __syncthreads();
    }
    float nsum = sred[0];
    float upd = (cs_bc + 1e-7f) / (nsum + (float)S * 1e-7f) * nsum;

    for (int c = 0; c < C; c++) {
        int i = s * C + c;
        float ew = 0.99f * ema_w[i] + 0.01f * g_dw[i];
        outp[OFF_EW + i]  = ew;
        outp[OFF_NCB + i] = (ew / bias_corr) / upd;
    }
    if (s == 0) outp[OFF_LOSS] = g_loss / 8388608.0f;
}

// ---------------- launch ----------------
extern "C" void kernel_launch(void* const* d_in, const int* in_sizes, int n_in,
                              void* d_out, int out_size) {
    const float* x            = (const float*)d_in[0];
    const float* codebook     = (const float*)d_in[1];
    const float* ema_w        = (const float*)d_in[2];
    const float* cluster_size = (const float*)d_in[3];
    const int*   steps        = (const int*)d_in[4];
    float* outp = (float*)d_out;

    const int smem_bytes = (2 * C * TOK + S + TOK + TOK + TPB / 32) * 4;
    cudaFuncSetAttribute(vq_main_kernel,
                         cudaFuncAttributeMaxDynamicSharedMemorySize, smem_bytes);

    vq_prep_kernel<<<(S * C + 255) / 256, 256>>>(codebook);
    vq_main_kernel<<<NTOK / TOK, TPB, smem_bytes>>>(x, codebook, outp);
    vq_finalize_kernel<<<1, S>>>(ema_w, cluster_size, steps, outp);
}